// round 13
// baseline (speedup 1.0000x reference)
#include <cuda_runtime.h>
#include <cuda_bf16.h>
#include <cstdint>
#include <cstddef>

// Problem constants
#define DD 88
#define HH 256
#define LL 128
#define BB 128
#define TT 1024
#define CSZ 8
#define NCLUST 16
#define NCTA 128
#define NTH 256
#define NKB 22                    // K blocks of 16 (K padded 344 -> 352; h at j=96+k)
#define ZOFF ((size_t)BB * TT * DD)

// SMEM layout (u32 units)
#define AHI_OFF   0               // [8 w][22 kb][32 lane][4 regs] = 22528 (bf16x2 packed)
#define ALO_OFF   22528
#define INB_OFF   45056           // 2 buffers x 2816 (each: hi plane 1408 | lo plane 1408)
#define DSM_OFF   50688           // 1024 f32 gates [128 row][8 b]; overlay: zbuf
#define WOUT_OFF  51712           // [32 k][88 d] f32 = 2816
#define PPART_OFF 54528           // [2 par][8 src][88 d] f32 = 1408
#define HLOC_OFF  55936           // [32 hid][8 b] f32 = 256
#define BGE_OFF   56192           // [32][4]
#define BGD_OFF   56320
#define BOUT_OFF  56448           // 88 pad 96
#define PREDL_OFF 56544           // 96 (dedicated; dsm is live concurrently)
#define XMB_OFF   56640           // x-feedback mbarrier (8B)
#define SMEM_U32  56648
#define SMEM_BYTES (SMEM_U32 * 4) // 226592

#define BTILE_U32 2816
#define BTILE_B   11264
#define BPLANE    1408            // u32 per plane
#define BPLANE_B  5632

static_assert(SMEM_BYTES <= 232448, "smem too big");
static_assert((XMB_OFF * 4) % 8 == 0, "mbar align");

// x pre-packed in B-fragment layout: g_x5[t][cluster][hi 384 | lo 384]
__device__ __align__(16) uint32_t g_x5[(size_t)TT * NCLUST * 768];

// ---------------------------------------------------------------------------
__device__ __forceinline__ void bf16_split(float v, float& hi, float& lo) {
    __nv_bfloat16 h = __float2bfloat16_rn(v);
    hi = __bfloat162float(h);
    lo = v - hi;
}
__device__ __forceinline__ uint32_t pack_bf2(float e0, float e1) {
    __nv_bfloat162 p = __floats2bfloat162_rn(e0, e1);
    return *(uint32_t*)&p;
}
__device__ __forceinline__ float bf_hi_lo(uint32_t bits, int sh) {
    unsigned short us = (unsigned short)((bits >> sh) & 0xFFFF);
    return __bfloat162float(*(__nv_bfloat16*)&us);
}

__global__ void lstm_init_kernel(const float* __restrict__ x) {
    const int t = blockIdx.x;
    const int tid = threadIdx.x;          // 128
    const int cl = tid >> 3, s = tid & 7;
    uint32_t* dst = g_x5 + ((size_t)t * NCLUST + cl) * 768;
    for (int f = s; f < 384; f += 8) {
        int kb = f >> 6, l = (f >> 1) & 31, i = f & 1;
        int j0 = kb * 16 + i * 8 + (l & 3) * 2;
        int b = cl * 8 + (l >> 2);
        const float* xb = x + ((size_t)b * TT + t) * DD;
        float v0 = (j0 < DD) ? xb[j0] : 0.0f;
        float v1 = (j0 + 1 < DD) ? xb[j0 + 1] : 0.0f;
        float h0, l0, h1, l1;
        bf16_split(v0, h0, l0);
        bf16_split(v1, h1, l1);
        dst[f] = pack_bf2(h0, h1);
        dst[384 + f] = pack_bf2(l0, l1);
    }
}

// ---------------------------------------------------------------------------
__device__ __forceinline__ float sigfast(float x) {
    return __fdividef(1.0f, 1.0f + __expf(-x));
}
__device__ __forceinline__ float tanhfast(float x) {
    float e = __expf(-2.0f * fabsf(x));
    float t = __fdividef(1.0f - e, 1.0f + e);
    return copysignf(t, x);
}

#define CLUSTER_SYNC() do { \
    asm volatile("barrier.cluster.arrive.aligned;" ::: "memory"); \
    asm volatile("barrier.cluster.wait.aligned;" ::: "memory");   \
} while (0)

__device__ __forceinline__ uint32_t map_rank(const void* lptr, int rank) {
    uint32_t la = (uint32_t)__cvta_generic_to_shared(lptr), ra;
    asm("mapa.shared::cluster.u32 %0, %1, %2;" : "=r"(ra) : "r"(la), "r"(rank));
    return ra;
}
__device__ __forceinline__ void stc32u(uint32_t ra, uint32_t v) {
    asm volatile("st.shared::cluster.b32 [%0], %1;" :: "r"(ra), "r"(v) : "memory");
}
__device__ __forceinline__ void stc32f(uint32_t ra, float v) {
    stc32u(ra, __float_as_uint(v));
}
__device__ __forceinline__ void mbar_init_(uint32_t a, uint32_t cnt) {
    asm volatile("mbarrier.init.shared.b64 [%0], %1;" :: "r"(a), "r"(cnt) : "memory");
}
__device__ __forceinline__ void mbar_arrive_rank(uint32_t la, int rank) {
    uint32_t ra;
    asm("mapa.shared::cluster.u32 %0, %1, %2;" : "=r"(ra) : "r"(la), "r"(rank));
    asm volatile("mbarrier.arrive.release.cluster.shared::cluster.b64 _, [%0];"
                 :: "r"(ra) : "memory");
}
__device__ __forceinline__ void mbar_wait_parity(uint32_t a, uint32_t parity) {
    uint32_t done;
    asm volatile(
        "{\n\t.reg .pred P;\n\t"
        "mbarrier.try_wait.parity.acquire.cluster.shared::cta.b64 P, [%1], %2;\n\t"
        "selp.b32 %0, 1, 0, P;\n\t}"
        : "=r"(done) : "r"(a), "r"(parity) : "memory");
    while (!done) {
        asm volatile(
            "{\n\t.reg .pred P;\n\t"
            "mbarrier.try_wait.parity.acquire.cluster.shared::cta.b64 P, [%1], %2, 0x989680;\n\t"
            "selp.b32 %0, 1, 0, P;\n\t}"
            : "=r"(done) : "r"(a), "r"(parity) : "memory");
    }
}

__device__ __forceinline__ void mma_bf16(float* d, uint4 a, uint2 b) {
    asm volatile(
        "mma.sync.aligned.m16n8k16.row.col.f32.bf16.bf16.f32 "
        "{%0,%1,%2,%3}, {%4,%5,%6,%7}, {%8,%9}, {%0,%1,%2,%3};"
        : "+f"(d[0]), "+f"(d[1]), "+f"(d[2]), "+f"(d[3])
        : "r"(a.x), "r"(a.y), "r"(a.z), "r"(a.w), "r"(b.x), "r"(b.y));
}

// Stage gate weights into A fragment layout (hi+lo bf16x2 planes).
__device__ void stage_w(uint32_t* smu, const float* __restrict__ Wih,
                        const float* __restrict__ Whh, int RANK, int tid) {
    for (int idx = tid; idx < 22528; idx += NTH) {
        int w = idx / 2816, rem = idx - w * 2816;
        int kb = rem >> 7, l = (rem >> 2) & 31, i = rem & 3;
        int r = 16 * w + (l >> 2) + 8 * (i & 1);
        int k0 = kb * 16 + 8 * (i >> 1) + 2 * (l & 3);
        int g = r >> 5, h = r & 31;
        int grow = g * HH + RANK * 32 + h;
        float v0 = (k0 < DD) ? Wih[(size_t)grow * DD + k0]
                 : (k0 >= 96 ? Whh[(size_t)grow * HH + (k0 - 96)] : 0.0f);
        int k1 = k0 + 1;
        float v1 = (k1 < DD) ? Wih[(size_t)grow * DD + k1]
                 : (k1 >= 96 ? Whh[(size_t)grow * HH + (k1 - 96)] : 0.0f);
        float h0, l0, h1, l1;
        bf16_split(v0, h0, l0);
        bf16_split(v1, h1, l1);
        smu[AHI_OFF + idx] = pack_bf2(h0, h1);
        smu[ALO_OFF + idx] = pack_bf2(l0, l1);
    }
}

// ---------------------------------------------------------------------------
__global__ void __launch_bounds__(NTH, 1) __cluster_dims__(CSZ, 1, 1)
lstm_cluster_kernel(
    const float* __restrict__ Wih_e, const float* __restrict__ Whh_e,
    const float* __restrict__ bih_e, const float* __restrict__ bhh_e,
    const float* __restrict__ Wih_d, const float* __restrict__ Whh_d,
    const float* __restrict__ bih_d, const float* __restrict__ bhh_d,
    const float* __restrict__ W_lat, const float* __restrict__ b_lat,
    const float* __restrict__ W_decinit, const float* __restrict__ b_decinit,
    const float* __restrict__ W_out, const float* __restrict__ b_out,
    float* __restrict__ out)
{
    extern __shared__ uint32_t smu[];
    float* dsmf    = (float*)(smu + DSM_OFF);
    float* zbuf    = dsmf;                         // overlay (latent/dec-init only)
    float* wout_s  = (float*)(smu + WOUT_OFF);
    float* ppartf  = (float*)(smu + PPART_OFF);    // [2 parity][8 src][88]
    float* hloc    = (float*)(smu + HLOC_OFF);
    float* bge_s   = (float*)(smu + BGE_OFF);
    float* bgd_s   = (float*)(smu + BGD_OFF);
    float* bout_s  = (float*)(smu + BOUT_OFF);
    float* predl   = (float*)(smu + PREDL_OFF);
    const uint32_t xmb = (uint32_t)__cvta_generic_to_shared(smu + XMB_OFF);

    const int tid  = threadIdx.x;
    const int wid  = tid >> 5;
    const int lane = tid & 31;
    const int RANK = blockIdx.x & (CSZ - 1);
    const int CLUST = blockIdx.x >> 3;
    const int ab = tid & 7;            // act batch
    const int hp = tid >> 3;           // act hid pair (tid<128)

    // ---- one-time staging ----
    stage_w(smu, Wih_e, Whh_e, RANK, tid);
    if (tid < 128) {
        int h2 = tid >> 2, g = tid & 3;
        int row = g * HH + RANK * 32 + h2;
        bge_s[h2 * 4 + g] = bih_e[row] + bhh_e[row];
        bgd_s[h2 * 4 + g] = bih_d[row] + bhh_d[row];
    }
    for (int idx = tid; idx < 32 * DD; idx += NTH) {
        int d8 = idx >> 5, k = idx & 31;
        wout_s[k * DD + d8] = W_out[(size_t)d8 * HH + RANK * 32 + k];
    }
    if (tid < DD) bout_s[tid] = b_out[tid];
    for (int i = tid; i < 2 * BTILE_U32; i += NTH) smu[INB_OFF + i] = 0u;
    __syncthreads();
    if (tid < 192) {
        uint4 v = *(const uint4*)(g_x5 + ((size_t)0 * NCLUST + CLUST) * 768 + tid * 4);
        uint32_t off = (tid < 96) ? (uint32_t)(tid * 4) : (uint32_t)(BPLANE + (tid - 96) * 4);
        *(uint4*)(smu + INB_OFF + off) = v;
    }

    // h-broadcast remote addresses (buffer 0 base, hi plane)
    uint32_t hdst[CSZ];
    if (tid < 128) {
        int j0 = 96 + RANK * 32 + 2 * hp;
        int fo = (j0 >> 4) * 64 + (4 * ab + ((j0 >> 1) & 3)) * 2 + ((j0 >> 3) & 1);
        const void* l0 = smu + INB_OFF + fo;
        #pragma unroll
        for (int r = 0; r < CSZ; r++) hdst[r] = map_rank(l0, r);
    }
    CLUSTER_SYNC();

    int cur = 0;
    float cst0 = 0.0f, cst1 = 0.0f;

    // gate GEMM over kb range [kb0, kb1): 6 independent accumulator chains.
    auto mma_blk = [&](int c, int kb0, int kb1, float (*acc)[4]) {
        const uint32_t* Ah = smu + AHI_OFF + wid * 2816;
        const uint32_t* Al = smu + ALO_OFF + wid * 2816;
        const uint32_t* Bh = smu + INB_OFF + c * BTILE_U32;
        const uint32_t* Bl = Bh + BPLANE;
        #pragma unroll
        for (int kb = kb0; kb < kb1; kb++) {
            uint4 ah = *(const uint4*)(Ah + kb * 128 + lane * 4);
            uint4 al = *(const uint4*)(Al + kb * 128 + lane * 4);
            uint2 bh = *(const uint2*)(Bh + kb * 64 + lane * 2);
            uint2 bl = *(const uint2*)(Bl + kb * 64 + lane * 2);
            float (*ap)[4] = acc + (kb & 1) * 3;
            mma_bf16(ap[0], ah, bh);
            mma_bf16(ap[1], ah, bl);
            mma_bf16(ap[2], al, bh);
        }
    };
    auto store_d = [&](float (*acc)[4]) {
        float* dst0 = dsmf + (16 * wid + (lane >> 2)) * 8 + (lane & 3) * 2;
        float d0 = ((acc[0][0] + acc[1][0]) + (acc[2][0] + acc[3][0])) + (acc[4][0] + acc[5][0]);
        float d1 = ((acc[0][1] + acc[1][1]) + (acc[2][1] + acc[3][1])) + (acc[4][1] + acc[5][1]);
        float d2 = ((acc[0][2] + acc[1][2]) + (acc[2][2] + acc[3][2])) + (acc[4][2] + acc[5][2]);
        float d3 = ((acc[0][3] + acc[1][3]) + (acc[2][3] + acc[3][3])) + (acc[4][3] + acc[5][3]);
        *(float2*)dst0 = make_float2(d0, d1);
        *(float2*)(dst0 + 64) = make_float2(d2, d3);
    };
    auto act_bcast = [&](const float* __restrict__ BIAS, int c) {
        if (tid < 128) {
            int r0 = 2 * hp, r1 = r0 + 1;
            float s0 = dsmf[(0 * 32 + r0) * 8 + ab] + BIAS[r0 * 4 + 0];
            float s1 = dsmf[(1 * 32 + r0) * 8 + ab] + BIAS[r0 * 4 + 1];
            float s2 = dsmf[(2 * 32 + r0) * 8 + ab] + BIAS[r0 * 4 + 2];
            float s3 = dsmf[(3 * 32 + r0) * 8 + ab] + BIAS[r0 * 4 + 3];
            float u0 = dsmf[(0 * 32 + r1) * 8 + ab] + BIAS[r1 * 4 + 0];
            float u1 = dsmf[(1 * 32 + r1) * 8 + ab] + BIAS[r1 * 4 + 1];
            float u2 = dsmf[(2 * 32 + r1) * 8 + ab] + BIAS[r1 * 4 + 2];
            float u3 = dsmf[(3 * 32 + r1) * 8 + ab] + BIAS[r1 * 4 + 3];
            float hv0, hv1;
            {
                float gi = sigfast(s0), gf = sigfast(s1);
                float gg = tanhfast(s2), go = sigfast(s3);
                cst0 = gf * cst0 + gi * gg;
                hv0 = go * tanhfast(cst0);
            }
            {
                float gi = sigfast(u0), gf = sigfast(u1);
                float gg = tanhfast(u2), go = sigfast(u3);
                cst1 = gf * cst1 + gi * gg;
                hv1 = go * tanhfast(cst1);
            }
            hloc[r0 * 8 + ab] = hv0;
            hloc[r1 * 8 + ab] = hv1;
            float hh0, ll0, hh1, ll1;
            bf16_split(hv0, hh0, ll0);
            bf16_split(hv1, hh1, ll1);
            uint32_t phi = pack_bf2(hh0, hh1);
            uint32_t plo = pack_bf2(ll0, ll1);
            const uint32_t cofs = (uint32_t)(c ^ 1) * BTILE_B;
            #pragma unroll
            for (int r = 0; r < CSZ; r++) {
                stc32u(hdst[r] + cofs, phi);
                stc32u(hdst[r] + cofs + BPLANE_B, plo);
            }
        }
    };

    // =============== encoder ===============
    #pragma unroll 1
    for (int t = 0; t < TT; t++) {
        float acc[6][4];
        #pragma unroll
        for (int a = 0; a < 6; a++)
            #pragma unroll
            for (int i = 0; i < 4; i++) acc[a][i] = 0.0f;
        mma_blk(cur, 0, NKB, acc);
        store_d(acc);
        uint4 xreg;
        const bool havex = (t + 1 < TT) && (tid < 192);
        if (havex)
            xreg = *(const uint4*)(g_x5 + ((size_t)(t + 1) * NCLUST + CLUST) * 768 + tid * 4);
        __syncthreads();
        act_bcast(bge_s, cur);
        if (havex) {
            uint32_t off = (tid < 96) ? (uint32_t)(tid * 4) : (uint32_t)(BPLANE + (tid - 96) * 4);
            *(uint4*)(smu + INB_OFF + (cur ^ 1) * BTILE_U32 + off) = xreg;
        }
        CLUSTER_SYNC();
        cur ^= 1;
    }

    // =============== latent z ===============
    if (tid < 128) {
        const int li = tid >> 3, zb = tid & 7;
        const int l = RANK * 16 + li;
        const float* wl = W_lat + (size_t)l * HH;
        const uint32_t* Bh = smu + INB_OFF + cur * BTILE_U32;
        const uint32_t* Bl = Bh + BPLANE;
        float acc = 0.0f;
        #pragma unroll 4
        for (int k = 0; k < HH; k++) {
            int j = 96 + k;
            int fo = (j >> 4) * 64 + (4 * zb + ((j >> 1) & 3)) * 2 + ((j >> 3) & 1);
            int sh = (j & 1) * 16;
            float hv = bf_hi_lo(Bh[fo], sh) + bf_hi_lo(Bl[fo], sh);
            acc += hv * wl[k];
        }
        float z = acc + b_lat[l];
        out[ZOFF + ((size_t)(CLUST * 8 + zb)) * LL + l] = z;
        const float* dstz = zbuf + l * 8 + zb;
        #pragma unroll
        for (int r = 0; r < CSZ; r++) stc32f(map_rank(dstz, r), z);
    }
    CLUSTER_SYNC();

    // restage decoder weights; zero x region of buffer cur^1 (pred0 = 0)
    stage_w(smu, Wih_d, Whh_d, RANK, tid);
    if (tid < 192) {
        uint32_t off = (tid < 96) ? (uint32_t)(tid * 4) : (uint32_t)(BPLANE + (tid - 96) * 4);
        *(uint4*)(smu + INB_OFF + (cur ^ 1) * BTILE_U32 + off) = make_uint4(0, 0, 0, 0);
    }
    // decoder init: h0 for hid pair from zbuf (fp32), broadcast packed
    if (tid < 128) {
        float h0v[2];
        #pragma unroll
        for (int q = 0; q < 2; q++) {
            int gh = RANK * 32 + 2 * hp + q;
            const float* wd = W_decinit + (size_t)gh * LL;
            float a0 = b_decinit[gh], a1 = 0.f, a2 = 0.f, a3 = 0.f;
            #pragma unroll 8
            for (int l = 0; l < LL; l += 4) {
                float4 wv = *(const float4*)(wd + l);
                a0 += zbuf[(l + 0) * 8 + ab] * wv.x;
                a1 += zbuf[(l + 1) * 8 + ab] * wv.y;
                a2 += zbuf[(l + 2) * 8 + ab] * wv.z;
                a3 += zbuf[(l + 3) * 8 + ab] * wv.w;
            }
            h0v[q] = a0 + a1 + a2 + a3;
        }
        float hh0, ll0, hh1, ll1;
        bf16_split(h0v[0], hh0, ll0);
        bf16_split(h0v[1], hh1, ll1);
        uint32_t phi = pack_bf2(hh0, hh1);
        uint32_t plo = pack_bf2(ll0, ll1);
        const uint32_t cofs = (uint32_t)(cur ^ 1) * BTILE_B;
        #pragma unroll
        for (int r = 0; r < CSZ; r++) {
            stc32u(hdst[r] + cofs, phi);
            stc32u(hdst[r] + cofs + BPLANE_B, plo);
        }
    }
    if (tid == 0) {
        mbar_init_(xmb, 8);
        asm volatile("fence.mbarrier_init.release.cluster;" ::: "memory");
    }
    CLUSTER_SYNC();
    cur ^= 1;
    cst0 = 0.0f;
    cst1 = 0.0f;

    // decoder pred-stage constants
    const int pb = tid & 7;
    const int ds = tid >> 3;           // d slot (0..31)
    const bool has3 = ds < (DD - 64);
    uint32_t pp0 = map_rank(ppartf + RANK * DD + ds, pb);   // parity 0 base
    uint32_t pp1 = pp0 + 32 * 4;
    uint32_t pp2 = pp0 + 64 * 4;
    uint32_t xdst[CSZ];
    if (tid < 44) {
        int j0 = 2 * tid;
        int fo = (j0 >> 4) * 64 + (4 * RANK + ((j0 >> 1) & 3)) * 2 + ((j0 >> 3) & 1);
        const void* l0x = smu + INB_OFF + fo;
        #pragma unroll
        for (int r = 0; r < CSZ; r++) xdst[r] = map_rank(l0x, r);
    }

    // =============== decoder (autoregressive; ONE cluster sync/step) ========
    int xph = 0;
    #pragma unroll 1
    for (int t = 0; t < TT; t++) {
        float acc[6][4];
        #pragma unroll
        for (int a = 0; a < 6; a++)
            #pragma unroll
            for (int i = 0; i < 4; i++) acc[a][i] = 0.0f;
        mma_blk(cur, 6, NKB, acc);            // h-part (doesn't need pred x)
        if (t > 0) { mbar_wait_parity(xmb, (uint32_t)xph); xph ^= 1; }
        mma_blk(cur, 0, 6, acc);              // x-part (needs pred feedback)
        store_d(acc);
        __syncthreads();
        act_bcast(bgd_s, cur);                // h(t) -> remote cur^1; fills hloc
        __syncthreads();
        // pred partials over own 32 hid for batch pb -> ppart[t&1]
        {
            const uint32_t pofs = (uint32_t)(t & 1) * (704 * 4);
            float pa0 = 0.f, pa1 = 0.f, pa2 = 0.f;
            #pragma unroll 8
            for (int k = 0; k < 32; k++) {
                float hv = hloc[k * 8 + pb];
                pa0 += hv * wout_s[k * DD + ds];
                pa1 += hv * wout_s[k * DD + ds + 32];
                if (has3) pa2 += hv * wout_s[k * DD + ds + 64];
            }
            stc32f(pp0 + pofs, pa0);
            stc32f(pp1 + pofs, pa1);
            if (has3) stc32f(pp2 + pofs, pa2);
        }
        CLUSTER_SYNC();                       // h(t) + ppart(t) visible
        // pred path (warps 0-2 only; overlaps other warps' next h-part MMA)
        if (tid < DD) {
            const float* pp = ppartf + (t & 1) * 704;
            float s = bout_s[tid];
            #pragma unroll
            for (int src = 0; src < CSZ; src++) s += pp[src * DD + tid];
            float pr = sigfast(s);
            out[(((size_t)(CLUST * 8 + RANK)) * TT + t) * DD + tid] = pr;
            predl[tid] = pr;
        }
        if (tid < 96) asm volatile("bar.sync 1, 96;" ::: "memory");
        if (tid < 44) {
            float p0 = predl[2 * tid], p1 = predl[2 * tid + 1];
            float hh0, ll0, hh1, ll1;
            bf16_split(p0, hh0, ll0);
            bf16_split(p1, hh1, ll1);
            uint32_t phi = pack_bf2(hh0, hh1);
            uint32_t plo = pack_bf2(ll0, ll1);
            const uint32_t cofs = (uint32_t)(cur ^ 1) * BTILE_B;
            #pragma unroll
            for (int r = 0; r < CSZ; r++) {
                stc32u(xdst[r] + cofs, phi);
                stc32u(xdst[r] + cofs + BPLANE_B, plo);
            }
        }
        if (tid < 96) asm volatile("bar.sync 1, 96;" ::: "memory");
        if (tid == 0) {
            asm volatile("fence.acq_rel.cluster;" ::: "memory");
            #pragma unroll
            for (int r = 0; r < CSZ; r++) mbar_arrive_rank(xmb, r);
        }
        cur ^= 1;
    }
    CLUSTER_SYNC();   // drain in-flight remote traffic before exit
}

// ---------------------------------------------------------------------------
extern "C" void kernel_launch(void* const* d_in, const int* in_sizes, int n_in,
                              void* d_out, int out_size) {
    const float* x         = (const float*)d_in[0];
    const float* Wih_e     = (const float*)d_in[1];
    const float* Whh_e     = (const float*)d_in[2];
    const float* bih_e     = (const float*)d_in[3];
    const float* bhh_e     = (const float*)d_in[4];
    const float* Wih_d     = (const float*)d_in[5];
    const float* Whh_d     = (const float*)d_in[6];
    const float* bih_d     = (const float*)d_in[7];
    const float* bhh_d     = (const float*)d_in[8];
    const float* W_lat     = (const float*)d_in[9];
    const float* b_lat     = (const float*)d_in[10];
    const float* W_decinit = (const float*)d_in[11];
    const float* b_decinit = (const float*)d_in[12];
    const float* W_out     = (const float*)d_in[13];
    const float* b_out     = (const float*)d_in[14];
    float* out = (float*)d_out;

    cudaFuncSetAttribute(lstm_cluster_kernel,
                         cudaFuncAttributeMaxDynamicSharedMemorySize, SMEM_BYTES);

    lstm_init_kernel<<<TT, 128>>>(x);
    lstm_cluster_kernel<<<NCTA, NTH, SMEM_BYTES>>>(
        Wih_e, Whh_e, bih_e, bhh_e,
        Wih_d, Whh_d, bih_d, bhh_d,
        W_lat, b_lat, W_decinit, b_decinit, W_out, b_out, out);
}

// round 15
// speedup vs baseline: 1.1757x; 1.1757x over previous
#include <cuda_runtime.h>
#include <cuda_bf16.h>
#include <cstdint>
#include <cstddef>

// Problem constants
#define DD 88
#define HH 256
#define LL 128
#define BB 128
#define TT 1024
#define CSZ 8
#define NCLUST 16
#define NCTA 128
#define NTH 256
#define NKB 22                    // K blocks of 16 (K padded 344 -> 352; h at j=96+k)
#define ZOFF ((size_t)BB * TT * DD)

// SMEM layout (u32 units)
#define AHI_OFF   0               // [8 w][22 kb][32 lane][4 regs] = 22528 (bf16x2 packed)
#define ALO_OFF   22528
#define INB_OFF   45056           // 2 buffers x 2816 (each: hi plane 1408 | lo plane 1408)
#define DSM_OFF   50688           // 1024 f32 gates [128 row][8 b]; overlays: zbuf, predloc
#define WOUT_OFF  51712           // [32 k][88 d] f32 = 2816
#define PPART_OFF 54528           // [8 src][88 d] f32 = 704
#define HLOC_OFF  55232           // [32 hid][8 b] f32 = 256
#define BGE_OFF   55488           // [32][4]
#define BGD_OFF   55616
#define BOUT_OFF  55744           // 88 pad 96
#define SMEM_U32  55840
#define SMEM_BYTES (SMEM_U32 * 4) // 223360

#define BTILE_U32 2816
#define BTILE_B   11264
#define BPLANE    1408            // u32 per plane
#define BPLANE_B  5632

static_assert(SMEM_BYTES <= 232448, "smem too big");

// x pre-packed in B-fragment layout: g_x5[t][cluster][hi 384 | lo 384]
__device__ __align__(16) uint32_t g_x5[(size_t)TT * NCLUST * 768];

// ---------------------------------------------------------------------------
__device__ __forceinline__ void bf16_split(float v, float& hi, float& lo) {
    __nv_bfloat16 h = __float2bfloat16_rn(v);
    hi = __bfloat162float(h);
    lo = v - hi;
}
__device__ __forceinline__ uint32_t pack_bf2(float e0, float e1) {
    __nv_bfloat162 p = __floats2bfloat162_rn(e0, e1);
    return *(uint32_t*)&p;
}
__device__ __forceinline__ float bf_hi_lo(uint32_t bits, int sh) {
    unsigned short us = (unsigned short)((bits >> sh) & 0xFFFF);
    return __bfloat162float(*(__nv_bfloat16*)&us);
}

__global__ void lstm_init_kernel(const float* __restrict__ x) {
    const int t = blockIdx.x;
    const int tid = threadIdx.x;          // 128
    const int cl = tid >> 3, s = tid & 7;
    uint32_t* dst = g_x5 + ((size_t)t * NCLUST + cl) * 768;
    for (int f = s; f < 384; f += 8) {
        int kb = f >> 6, l = (f >> 1) & 31, i = f & 1;
        int j0 = kb * 16 + i * 8 + (l & 3) * 2;
        int b = cl * 8 + (l >> 2);
        const float* xb = x + ((size_t)b * TT + t) * DD;
        float v0 = (j0 < DD) ? xb[j0] : 0.0f;
        float v1 = (j0 + 1 < DD) ? xb[j0 + 1] : 0.0f;
        float h0, l0, h1, l1;
        bf16_split(v0, h0, l0);
        bf16_split(v1, h1, l1);
        dst[f] = pack_bf2(h0, h1);
        dst[384 + f] = pack_bf2(l0, l1);
    }
}

// ---------------------------------------------------------------------------
__device__ __forceinline__ float sigfast(float x) {
    return __fdividef(1.0f, 1.0f + __expf(-x));
}
__device__ __forceinline__ float tanhfast(float x) {
    float e = __expf(-2.0f * fabsf(x));
    float t = __fdividef(1.0f - e, 1.0f + e);
    return copysignf(t, x);
}

#define CLUSTER_SYNC() do { \
    asm volatile("barrier.cluster.arrive.aligned;" ::: "memory"); \
    asm volatile("barrier.cluster.wait.aligned;" ::: "memory");   \
} while (0)

__device__ __forceinline__ uint32_t map_rank(const void* lptr, int rank) {
    uint32_t la = (uint32_t)__cvta_generic_to_shared(lptr), ra;
    asm("mapa.shared::cluster.u32 %0, %1, %2;" : "=r"(ra) : "r"(la), "r"(rank));
    return ra;
}
__device__ __forceinline__ void stc32u(uint32_t ra, uint32_t v) {
    asm volatile("st.shared::cluster.b32 [%0], %1;" :: "r"(ra), "r"(v) : "memory");
}
__device__ __forceinline__ void stc32f(uint32_t ra, float v) {
    stc32u(ra, __float_as_uint(v));
}

__device__ __forceinline__ void mma_bf16(float* d, uint4 a, uint2 b) {
    asm volatile(
        "mma.sync.aligned.m16n8k16.row.col.f32.bf16.bf16.f32 "
        "{%0,%1,%2,%3}, {%4,%5,%6,%7}, {%8,%9}, {%0,%1,%2,%3};"
        : "+f"(d[0]), "+f"(d[1]), "+f"(d[2]), "+f"(d[3])
        : "r"(a.x), "r"(a.y), "r"(a.z), "r"(a.w), "r"(b.x), "r"(b.y));
}

// Stage gate weights into A fragment layout (hi+lo bf16x2 planes).
// Row r = g*32 + hid_local; col j: j<88 -> Wih[:,j]; 88..95 -> 0; >=96 -> Whh[:,j-96]
__device__ void stage_w(uint32_t* smu, const float* __restrict__ Wih,
                        const float* __restrict__ Whh, int RANK, int tid) {
    for (int idx = tid; idx < 22528; idx += NTH) {
        int w = idx / 2816, rem = idx - w * 2816;
        int kb = rem >> 7, l = (rem >> 2) & 31, i = rem & 3;
        int r = 16 * w + (l >> 2) + 8 * (i & 1);
        int k0 = kb * 16 + 8 * (i >> 1) + 2 * (l & 3);
        int g = r >> 5, h = r & 31;
        int grow = g * HH + RANK * 32 + h;
        float v0 = (k0 < DD) ? Wih[(size_t)grow * DD + k0]
                 : (k0 >= 96 ? Whh[(size_t)grow * HH + (k0 - 96)] : 0.0f);
        int k1 = k0 + 1;
        float v1 = (k1 < DD) ? Wih[(size_t)grow * DD + k1]
                 : (k1 >= 96 ? Whh[(size_t)grow * HH + (k1 - 96)] : 0.0f);
        float h0, l0, h1, l1;
        bf16_split(v0, h0, l0);
        bf16_split(v1, h1, l1);
        smu[AHI_OFF + idx] = pack_bf2(h0, h1);
        smu[ALO_OFF + idx] = pack_bf2(l0, l1);
    }
}

// ---------------------------------------------------------------------------
// 16 clusters x 8 CTAs x 256 threads. Cluster = 8 batch columns.
// Gates via 8-warp mma.sync bf16 split (3-pass hi/lo): M=128, N=8, K=352.
// Act map: tid<128: ab=tid&7, hp=tid>>3 (hid pair 2hp, 2hp+1).
// ---------------------------------------------------------------------------
__global__ void __launch_bounds__(NTH, 1) __cluster_dims__(CSZ, 1, 1)
lstm_cluster_kernel(
    const float* __restrict__ Wih_e, const float* __restrict__ Whh_e,
    const float* __restrict__ bih_e, const float* __restrict__ bhh_e,
    const float* __restrict__ Wih_d, const float* __restrict__ Whh_d,
    const float* __restrict__ bih_d, const float* __restrict__ bhh_d,
    const float* __restrict__ W_lat, const float* __restrict__ b_lat,
    const float* __restrict__ W_decinit, const float* __restrict__ b_decinit,
    const float* __restrict__ W_out, const float* __restrict__ b_out,
    float* __restrict__ out)
{
    extern __shared__ uint32_t smu[];
    float* dsmf    = (float*)(smu + DSM_OFF);
    float* zbuf    = dsmf;                         // overlay (latent/dec-init)
    float* predloc = dsmf;                         // overlay (decoder tail)
    float* wout_s  = (float*)(smu + WOUT_OFF);
    float* ppart   = (float*)(smu + PPART_OFF);
    float* hloc    = (float*)(smu + HLOC_OFF);
    float* bge_s   = (float*)(smu + BGE_OFF);
    float* bgd_s   = (float*)(smu + BGD_OFF);
    float* bout_s  = (float*)(smu + BOUT_OFF);

    const int tid  = threadIdx.x;
    const int wid  = tid >> 5;
    const int lane = tid & 31;
    const int RANK = blockIdx.x & (CSZ - 1);
    const int CLUST = blockIdx.x >> 3;
    const int ab = tid & 7;            // act batch
    const int hp = tid >> 3;           // act hid pair (0..15) for tid<128

    // ---- one-time staging ----
    stage_w(smu, Wih_e, Whh_e, RANK, tid);
    if (tid < 128) {
        int h2 = tid >> 2, g = tid & 3;
        int row = g * HH + RANK * 32 + h2;
        bge_s[h2 * 4 + g] = bih_e[row] + bhh_e[row];
        bgd_s[h2 * 4 + g] = bih_d[row] + bhh_d[row];
    }
    for (int idx = tid; idx < 32 * DD; idx += NTH) {
        int d8 = idx >> 5, k = idx & 31;
        wout_s[k * DD + d8] = W_out[(size_t)d8 * HH + RANK * 32 + k];
    }
    if (tid < DD) bout_s[tid] = b_out[tid];
    // zero both B buffers (h region zero = h0; x region overwritten below)
    for (int i = tid; i < 2 * BTILE_U32; i += NTH) smu[INB_OFF + i] = 0u;
    __syncthreads();
    // x(0) into buffer 0
    if (tid < 192) {
        uint4 v = *(const uint4*)(g_x5 + ((size_t)0 * NCLUST + CLUST) * 768 + tid * 4);
        uint32_t off = (tid < 96) ? (uint32_t)(tid * 4) : (uint32_t)(BPLANE + (tid - 96) * 4);
        *(uint4*)(smu + INB_OFF + off) = v;
    }

    // h-broadcast remote addresses (act threads, buffer 0 base, hi plane)
    uint32_t hdst[CSZ];
    if (tid < 128) {
        int j0 = 96 + RANK * 32 + 2 * hp;
        int fo = (j0 >> 4) * 64 + (4 * ab + ((j0 >> 1) & 3)) * 2 + ((j0 >> 3) & 1);
        const void* l0 = smu + INB_OFF + fo;
        #pragma unroll
        for (int r = 0; r < CSZ; r++) hdst[r] = map_rank(l0, r);
    }
    CLUSTER_SYNC();

    int cur = 0;
    float cst0 = 0.0f, cst1 = 0.0f;    // cell states (hid 2hp, 2hp+1) for batch ab

    // ---- gate GEMM via mma.sync (all 8 warps) -> dsmf[128][8] ----
    // 3 independent accumulator chains (one per hi/lo pass) to break the
    // 66-deep RAW chain; summed once at store.
    auto mma_gates = [&](int c) {
        const uint32_t* Ah = smu + AHI_OFF + wid * 2816;
        const uint32_t* Al = smu + ALO_OFF + wid * 2816;
        const uint32_t* Bh = smu + INB_OFF + c * BTILE_U32;
        const uint32_t* Bl = Bh + BPLANE;
        float d0[4] = {0.f, 0.f, 0.f, 0.f};
        float d1[4] = {0.f, 0.f, 0.f, 0.f};
        float d2[4] = {0.f, 0.f, 0.f, 0.f};
        #pragma unroll
        for (int kb = 0; kb < NKB; kb++) {
            uint4 ah = *(const uint4*)(Ah + kb * 128 + lane * 4);
            uint4 al = *(const uint4*)(Al + kb * 128 + lane * 4);
            uint2 bh = *(const uint2*)(Bh + kb * 64 + lane * 2);
            uint2 bl = *(const uint2*)(Bl + kb * 64 + lane * 2);
            mma_bf16(d0, ah, bh);
            mma_bf16(d1, ah, bl);
            mma_bf16(d2, al, bh);
        }
        float* dst0 = dsmf + (16 * wid + (lane >> 2)) * 8 + (lane & 3) * 2;
        *(float2*)dst0 = make_float2(d0[0] + (d1[0] + d2[0]), d0[1] + (d1[1] + d2[1]));
        *(float2*)(dst0 + 64) = make_float2(d0[2] + (d1[2] + d2[2]), d0[3] + (d1[3] + d2[3]));
    };

    // ---- activations for hid pair + packed h broadcast ----
    auto act_bcast = [&](const float* __restrict__ BIAS, int c) {
        if (tid < 128) {
            int r0 = 2 * hp, r1 = r0 + 1;
            float s0 = dsmf[(0 * 32 + r0) * 8 + ab] + BIAS[r0 * 4 + 0];
            float s1 = dsmf[(1 * 32 + r0) * 8 + ab] + BIAS[r0 * 4 + 1];
            float s2 = dsmf[(2 * 32 + r0) * 8 + ab] + BIAS[r0 * 4 + 2];
            float s3 = dsmf[(3 * 32 + r0) * 8 + ab] + BIAS[r0 * 4 + 3];
            float u0 = dsmf[(0 * 32 + r1) * 8 + ab] + BIAS[r1 * 4 + 0];
            float u1 = dsmf[(1 * 32 + r1) * 8 + ab] + BIAS[r1 * 4 + 1];
            float u2 = dsmf[(2 * 32 + r1) * 8 + ab] + BIAS[r1 * 4 + 2];
            float u3 = dsmf[(3 * 32 + r1) * 8 + ab] + BIAS[r1 * 4 + 3];
            float hv0, hv1;
            {
                float gi = sigfast(s0), gf = sigfast(s1);
                float gg = tanhfast(s2), go = sigfast(s3);
                cst0 = gf * cst0 + gi * gg;
                hv0 = go * tanhfast(cst0);
            }
            {
                float gi = sigfast(u0), gf = sigfast(u1);
                float gg = tanhfast(u2), go = sigfast(u3);
                cst1 = gf * cst1 + gi * gg;
                hv1 = go * tanhfast(cst1);
            }
            hloc[r0 * 8 + ab] = hv0;
            hloc[r1 * 8 + ab] = hv1;
            float hh0, ll0, hh1, ll1;
            bf16_split(hv0, hh0, ll0);
            bf16_split(hv1, hh1, ll1);
            uint32_t phi = pack_bf2(hh0, hh1);
            uint32_t plo = pack_bf2(ll0, ll1);
            const uint32_t cofs = (uint32_t)(c ^ 1) * BTILE_B;
            #pragma unroll
            for (int r = 0; r < CSZ; r++) {
                stc32u(hdst[r] + cofs, phi);
                stc32u(hdst[r] + cofs + BPLANE_B, plo);
            }
        }
    };

    // =============== encoder ===============
    #pragma unroll 1
    for (int t = 0; t < TT; t++) {
        mma_gates(cur);
        uint4 xreg;
        const bool havex = (t + 1 < TT) && (tid < 192);
        if (havex)
            xreg = *(const uint4*)(g_x5 + ((size_t)(t + 1) * NCLUST + CLUST) * 768 + tid * 4);
        __syncthreads();          // dsm complete
        act_bcast(bge_s, cur);
        if (havex) {
            uint32_t off = (tid < 96) ? (uint32_t)(tid * 4) : (uint32_t)(BPLANE + (tid - 96) * 4);
            *(uint4*)(smu + INB_OFF + (cur ^ 1) * BTILE_U32 + off) = xreg;
        }
        CLUSTER_SYNC();
        cur ^= 1;
    }

    // =============== latent z ===============
    if (tid < 128) {
        const int li = tid >> 3, zb = tid & 7;
        const int l = RANK * 16 + li;
        const float* wl = W_lat + (size_t)l * HH;
        const uint32_t* Bh = smu + INB_OFF + cur * BTILE_U32;
        const uint32_t* Bl = Bh + BPLANE;
        float acc = 0.0f;
        #pragma unroll 4
        for (int k = 0; k < HH; k++) {
            int j = 96 + k;
            int fo = (j >> 4) * 64 + (4 * zb + ((j >> 1) & 3)) * 2 + ((j >> 3) & 1);
            int sh = (j & 1) * 16;
            float hv = bf_hi_lo(Bh[fo], sh) + bf_hi_lo(Bl[fo], sh);
            acc += hv * wl[k];
        }
        float z = acc + b_lat[l];
        out[ZOFF + ((size_t)(CLUST * 8 + zb)) * LL + l] = z;
        const float* dstz = zbuf + l * 8 + zb;
        #pragma unroll
        for (int r = 0; r < CSZ; r++) stc32f(map_rank(dstz, r), z);
    }
    CLUSTER_SYNC();

    // restage decoder weights; zero x region of buffer cur^1 (pred0 = 0)
    stage_w(smu, Wih_d, Whh_d, RANK, tid);
    if (tid < 192) {
        uint32_t off = (tid < 96) ? (uint32_t)(tid * 4) : (uint32_t)(BPLANE + (tid - 96) * 4);
        *(uint4*)(smu + INB_OFF + (cur ^ 1) * BTILE_U32 + off) = make_uint4(0, 0, 0, 0);
    }
    // decoder init: h0 for hid pair from zbuf (fp32), broadcast packed
    if (tid < 128) {
        float h0v[2];
        #pragma unroll
        for (int q = 0; q < 2; q++) {
            int gh = RANK * 32 + 2 * hp + q;
            const float* wd = W_decinit + (size_t)gh * LL;
            float a0 = b_decinit[gh], a1 = 0.f, a2 = 0.f, a3 = 0.f;
            #pragma unroll 8
            for (int l = 0; l < LL; l += 4) {
                float4 wv = *(const float4*)(wd + l);
                a0 += zbuf[(l + 0) * 8 + ab] * wv.x;
                a1 += zbuf[(l + 1) * 8 + ab] * wv.y;
                a2 += zbuf[(l + 2) * 8 + ab] * wv.z;
                a3 += zbuf[(l + 3) * 8 + ab] * wv.w;
            }
            h0v[q] = a0 + a1 + a2 + a3;
        }
        float hh0, ll0, hh1, ll1;
        bf16_split(h0v[0], hh0, ll0);
        bf16_split(h0v[1], hh1, ll1);
        uint32_t phi = pack_bf2(hh0, hh1);
        uint32_t plo = pack_bf2(ll0, ll1);
        const uint32_t cofs = (uint32_t)(cur ^ 1) * BTILE_B;
        #pragma unroll
        for (int r = 0; r < CSZ; r++) {
            stc32u(hdst[r] + cofs, phi);
            stc32u(hdst[r] + cofs + BPLANE_B, plo);
        }
    }
    CLUSTER_SYNC();
    cur ^= 1;
    cst0 = 0.0f;
    cst1 = 0.0f;

    // decoder pred-stage constants
    const int pb = tid & 7;            // batch served for partials
    const int ds = tid >> 3;           // d slot (0..31): d = ds, ds+32, (ds+64)
    const bool has3 = ds < (DD - 64);
    uint32_t pp0 = map_rank(ppart + RANK * DD + ds, pb);
    uint32_t pp1 = pp0 + 32 * 4;
    uint32_t pp2 = pp0 + 64 * 4;
    uint32_t xdst[CSZ];
    if (tid < 44) {
        int j0 = 2 * tid;
        int fo = (j0 >> 4) * 64 + (4 * RANK + ((j0 >> 1) & 3)) * 2 + ((j0 >> 3) & 1);
        const void* l0x = smu + INB_OFF + fo;
        #pragma unroll
        for (int r = 0; r < CSZ; r++) xdst[r] = map_rank(l0x, r);
    }

    // =============== decoder (autoregressive) ===============
    #pragma unroll 1
    for (int t = 0; t < TT; t++) {
        mma_gates(cur);
        __syncthreads();              // dsm complete
        act_bcast(bgd_s, cur);        // also fills hloc (fp32)
        __syncthreads();              // hloc visible to all 256
        // pred partials over own 32 hid for batch pb
        {
            float pa0 = 0.f, pa1 = 0.f, pa2 = 0.f;
            #pragma unroll 8
            for (int k = 0; k < 32; k++) {
                float hv = hloc[k * 8 + pb];
                pa0 += hv * wout_s[k * DD + ds];
                pa1 += hv * wout_s[k * DD + ds + 32];
                if (has3) pa2 += hv * wout_s[k * DD + ds + 64];
            }
            stc32f(pp0, pa0);
            stc32f(pp1, pa1);
            if (has3) stc32f(pp2, pa2);
        }
        CLUSTER_SYNC();               // h + partials visible everywhere
        // owner (batch = RANK): reduce, sigmoid, emit
        if (tid < DD) {
            float s = bout_s[tid];
            #pragma unroll
            for (int src = 0; src < CSZ; src++) s += ppart[src * DD + tid];
            float pr = sigfast(s);
            out[(((size_t)(CLUST * 8 + RANK)) * TT + t) * DD + tid] = pr;
            predloc[tid] = pr;
        }
        __syncthreads();
        if (tid < 44) {
            float p0 = predloc[2 * tid], p1 = predloc[2 * tid + 1];
            float hh0, ll0, hh1, ll1;
            bf16_split(p0, hh0, ll0);
            bf16_split(p1, hh1, ll1);
            uint32_t phi = pack_bf2(hh0, hh1);
            uint32_t plo = pack_bf2(ll0, ll1);
            const uint32_t cofs = (uint32_t)(cur ^ 1) * BTILE_B;
            #pragma unroll
            for (int r = 0; r < CSZ; r++) {
                stc32u(xdst[r] + cofs, phi);
                stc32u(xdst[r] + cofs + BPLANE_B, plo);
            }
        }
        CLUSTER_SYNC();               // pred feedback visible
        cur ^= 1;
    }
}

// ---------------------------------------------------------------------------
extern "C" void kernel_launch(void* const* d_in, const int* in_sizes, int n_in,
                              void* d_out, int out_size) {
    const float* x         = (const float*)d_in[0];
    const float* Wih_e     = (const float*)d_in[1];
    const float* Whh_e     = (const float*)d_in[2];
    const float* bih_e     = (const float*)d_in[3];
    const float* bhh_e     = (const float*)d_in[4];
    const float* Wih_d     = (const float*)d_in[5];
    const float* Whh_d     = (const float*)d_in[6];
    const float* bih_d     = (const float*)d_in[7];
    const float* bhh_d     = (const float*)d_in[8];
    const float* W_lat     = (const float*)d_in[9];
    const float* b_lat     = (const float*)d_in[10];
    const float* W_decinit = (const float*)d_in[11];
    const float* b_decinit = (const float*)d_in[12];
    const float* W_out     = (const float*)d_in[13];
    const float* b_out     = (const float*)d_in[14];
    float* out = (float*)d_out;

    cudaFuncSetAttribute(lstm_cluster_kernel,
                         cudaFuncAttributeMaxDynamicSharedMemorySize, SMEM_BYTES);

    lstm_init_kernel<<<TT, 128>>>(x);
    lstm_cluster_kernel<<<NCTA, NTH, SMEM_BYTES>>>(
        Wih_e, Whh_e, bih_e, bhh_e,
        Wih_d, Whh_d, bih_d, bhh_d,
        W_lat, b_lat, W_decinit, b_decinit, W_out, b_out, out);
}